// round 1
// baseline (speedup 1.0000x reference)
#include <cuda_runtime.h>
#include <math.h>

// Problem constants
#define B_  16
#define H_  8
#define L_  1024
#define DK_ 64
#define DV_ 64
#define BH_ 128
static __device__ __constant__ float kScale = 0.125f;  // 1/sqrt(64)

// Scratch for branch-1 logits (attention output region doubles as scratch for branch-2).
__device__ float g_l1[(size_t)BH_ * L_ * L_];

// ---------------------------------------------------------------------------
// Kernel 1: compute logits for both branches for one 64x64 (q,k) tile.
//   l1[q,k] = scale * dot(Q[bh,q,:], K[bh,k,:])
//   l2[q,k] = scale * ( dot(W[h,q,0:64],  Q[bh,k,:]) +
//                       dot(W[h,q,64:128],K[bh,k,:]) )
// smem layout: d-major tiles [64][68] (pad 68 floats for conflict-free access).
// ---------------------------------------------------------------------------
#define TS_ (64 * 68)

__global__ void logits_kernel(const float* __restrict__ Q,
                              const float* __restrict__ K,
                              const float* __restrict__ W,
                              float* __restrict__ l2out) {
    extern __shared__ __align__(16) float sm[];
    float* sQq = sm;            // [d][q]  Q rows for q-tile
    float* sWq = sm + TS_;      // [d][q]  W[:, 0:64]
    float* sWk = sm + 2 * TS_;  // [d][q]  W[:, 64:128]
    float* sKk = sm + 3 * TS_;  // [d][k]  K rows for k-tile
    float* sQk = sm + 4 * TS_;  // [d][k]  Q rows for k-tile

    const int bh = blockIdx.z;
    const int h  = bh & (H_ - 1);
    const int q0 = blockIdx.y << 6;
    const int k0 = blockIdx.x << 6;
    const int t  = threadIdx.x;

    const float* Qq = Q + ((size_t)bh * L_ + q0) * DK_;
    const float* Wb = W + ((size_t)h  * L_ + q0) * (2 * DK_);
    const float* Kk = K + ((size_t)bh * L_ + k0) * DK_;
    const float* Qk = Q + ((size_t)bh * L_ + k0) * DK_;

    // Transposed loads: 64x64 tile -> [d][row] smem (stride 68).
    #pragma unroll
    for (int it = 0; it < 4; it++) {
        int lin = t + it * 256;          // 0..1023 float4 slots
        int r   = lin >> 4;              // tile row 0..63
        int c4  = (lin & 15) * 4;        // d base 0..60
        float4 v;
        v = *(const float4*)(Qq + r * DK_ + c4);
        sQq[(c4+0)*68 + r] = v.x; sQq[(c4+1)*68 + r] = v.y;
        sQq[(c4+2)*68 + r] = v.z; sQq[(c4+3)*68 + r] = v.w;
        v = *(const float4*)(Wb + r * 128 + c4);
        sWq[(c4+0)*68 + r] = v.x; sWq[(c4+1)*68 + r] = v.y;
        sWq[(c4+2)*68 + r] = v.z; sWq[(c4+3)*68 + r] = v.w;
        v = *(const float4*)(Wb + r * 128 + 64 + c4);
        sWk[(c4+0)*68 + r] = v.x; sWk[(c4+1)*68 + r] = v.y;
        sWk[(c4+2)*68 + r] = v.z; sWk[(c4+3)*68 + r] = v.w;
        v = *(const float4*)(Kk + r * DK_ + c4);
        sKk[(c4+0)*68 + r] = v.x; sKk[(c4+1)*68 + r] = v.y;
        sKk[(c4+2)*68 + r] = v.z; sKk[(c4+3)*68 + r] = v.w;
        v = *(const float4*)(Qk + r * DK_ + c4);
        sQk[(c4+0)*68 + r] = v.x; sQk[(c4+1)*68 + r] = v.y;
        sQk[(c4+2)*68 + r] = v.z; sQk[(c4+3)*68 + r] = v.w;
    }
    __syncthreads();

    const int kt = (t & 15) * 4;   // k micro-offset
    const int qt = (t >> 4) * 4;   // q micro-offset

    float acc1[4][4] = {};
    float acc2[4][4] = {};

    #pragma unroll 8
    for (int d = 0; d < 64; d++) {
        float4 f;
        float va[4], vwq[4], vwk[4], vbk[4], vbq[4];
        f = *(const float4*)&sQq[d * 68 + qt]; va[0]=f.x; va[1]=f.y; va[2]=f.z; va[3]=f.w;
        f = *(const float4*)&sWq[d * 68 + qt]; vwq[0]=f.x; vwq[1]=f.y; vwq[2]=f.z; vwq[3]=f.w;
        f = *(const float4*)&sWk[d * 68 + qt]; vwk[0]=f.x; vwk[1]=f.y; vwk[2]=f.z; vwk[3]=f.w;
        f = *(const float4*)&sKk[d * 68 + kt]; vbk[0]=f.x; vbk[1]=f.y; vbk[2]=f.z; vbk[3]=f.w;
        f = *(const float4*)&sQk[d * 68 + kt]; vbq[0]=f.x; vbq[1]=f.y; vbq[2]=f.z; vbq[3]=f.w;
        #pragma unroll
        for (int i = 0; i < 4; i++)
            #pragma unroll
            for (int j = 0; j < 4; j++) {
                acc1[i][j] = fmaf(va[i],  vbk[j], acc1[i][j]);
                acc2[i][j] = fmaf(vwq[i], vbq[j], acc2[i][j]);
                acc2[i][j] = fmaf(vwk[i], vbk[j], acc2[i][j]);
            }
    }

    const float s = kScale;
    #pragma unroll
    for (int i = 0; i < 4; i++) {
        size_t row = ((size_t)bh * L_ + q0 + qt + i) * L_ + k0 + kt;
        float4 o1 = make_float4(acc1[i][0]*s, acc1[i][1]*s, acc1[i][2]*s, acc1[i][3]*s);
        float4 o2 = make_float4(acc2[i][0]*s, acc2[i][1]*s, acc2[i][2]*s, acc2[i][3]*s);
        *(float4*)(g_l1 + row)  = o1;
        *(float4*)(l2out + row) = o2;
    }
}

// ---------------------------------------------------------------------------
// Kernel 2: per-row dual softmax + add.
//   attn_row = softmax(l1_row) + softmax(l2_row)   (l2 staged in attn buffer)
// One block (128 threads) per row; 8 elements/thread/branch.
// ---------------------------------------------------------------------------
__global__ void softmax_add_kernel(float* __restrict__ attn) {
    const int row = blockIdx.x;
    const float* r1 = g_l1 + (size_t)row * L_;
    float* r2 = attn + (size_t)row * L_;
    const int t = threadIdx.x;

    float a[8], b[8];
    #pragma unroll
    for (int i = 0; i < 8; i++) {
        a[i] = r1[t + i * 128];
        b[i] = r2[t + i * 128];
    }

    float m1 = -1e30f, m2 = -1e30f;
    #pragma unroll
    for (int i = 0; i < 8; i++) { m1 = fmaxf(m1, a[i]); m2 = fmaxf(m2, b[i]); }
    #pragma unroll
    for (int o = 16; o > 0; o >>= 1) {
        m1 = fmaxf(m1, __shfl_xor_sync(0xffffffffu, m1, o));
        m2 = fmaxf(m2, __shfl_xor_sync(0xffffffffu, m2, o));
    }
    __shared__ float sA[4], sB[4];
    const int wid = t >> 5, lid = t & 31;
    if (lid == 0) { sA[wid] = m1; sB[wid] = m2; }
    __syncthreads();
    m1 = fmaxf(fmaxf(sA[0], sA[1]), fmaxf(sA[2], sA[3]));
    m2 = fmaxf(fmaxf(sB[0], sB[1]), fmaxf(sB[2], sB[3]));
    __syncthreads();

    float e1 = 0.f, e2 = 0.f;
    #pragma unroll
    for (int i = 0; i < 8; i++) {
        a[i] = __expf(a[i] - m1); e1 += a[i];
        b[i] = __expf(b[i] - m2); e2 += b[i];
    }
    #pragma unroll
    for (int o = 16; o > 0; o >>= 1) {
        e1 += __shfl_xor_sync(0xffffffffu, e1, o);
        e2 += __shfl_xor_sync(0xffffffffu, e2, o);
    }
    if (lid == 0) { sA[wid] = e1; sB[wid] = e2; }
    __syncthreads();
    e1 = sA[0] + sA[1] + sA[2] + sA[3];
    e2 = sB[0] + sB[1] + sB[2] + sB[3];

    const float inv1 = 1.f / e1, inv2 = 1.f / e2;
    #pragma unroll
    for (int i = 0; i < 8; i++)
        r2[t + i * 128] = a[i] * inv1 + b[i] * inv2;
}

// ---------------------------------------------------------------------------
// Kernel 3: context = attention @ V  (batched 1024x64x1024 GEMM).
// 64(q) x 64(d) output tile per block, stream k in chunks of 64.
// ---------------------------------------------------------------------------
__global__ void av_kernel(const float* __restrict__ attn,
                          const float* __restrict__ V,
                          float* __restrict__ ctx) {
    __shared__ __align__(16) float sAt[TS_];  // [k][q] transposed attn tile
    __shared__ __align__(16) float sVt[TS_];  // [k][d] V tile
    const int bh = blockIdx.y;
    const int q0 = blockIdx.x << 6;
    const int t  = threadIdx.x;

    const int dt = (t & 15) * 4;
    const int qt = (t >> 4) * 4;
    float acc[4][4] = {};

    for (int kc = 0; kc < 16; kc++) {
        const int k0 = kc << 6;
        const float* Ab = attn + ((size_t)bh * L_ + q0) * L_ + k0;
        const float* Vb = V    + ((size_t)bh * L_ + k0) * DV_;
        #pragma unroll
        for (int it = 0; it < 4; it++) {
            int lin = t + it * 256;
            int r   = lin >> 4;          // q row (attn) / k row (V)
            int c4  = (lin & 15) * 4;    // k col (attn) / d col (V)
            float4 v = *(const float4*)(Ab + (size_t)r * L_ + c4);
            sAt[(c4+0)*68 + r] = v.x; sAt[(c4+1)*68 + r] = v.y;
            sAt[(c4+2)*68 + r] = v.z; sAt[(c4+3)*68 + r] = v.w;
            float4 w = *(const float4*)(Vb + r * DV_ + c4);
            *(float4*)&sVt[r * 68 + c4] = w;
        }
        __syncthreads();
        #pragma unroll 8
        for (int kk = 0; kk < 64; kk++) {
            float4 fa = *(const float4*)&sAt[kk * 68 + qt];
            float4 fv = *(const float4*)&sVt[kk * 68 + dt];
            float va[4] = {fa.x, fa.y, fa.z, fa.w};
            float vv[4] = {fv.x, fv.y, fv.z, fv.w};
            #pragma unroll
            for (int i = 0; i < 4; i++)
                #pragma unroll
                for (int j = 0; j < 4; j++)
                    acc[i][j] = fmaf(va[i], vv[j], acc[i][j]);
        }
        __syncthreads();
    }

    #pragma unroll
    for (int i = 0; i < 4; i++) {
        float4 o = make_float4(acc[i][0], acc[i][1], acc[i][2], acc[i][3]);
        *(float4*)(ctx + ((size_t)bh * L_ + q0 + qt + i) * DV_ + dt) = o;
    }
}

// ---------------------------------------------------------------------------
extern "C" void kernel_launch(void* const* d_in, const int* in_sizes, int n_in,
                              void* d_out, int out_size) {
    const float* Q = (const float*)d_in[0];
    const float* K = (const float*)d_in[1];
    const float* V = (const float*)d_in[2];
    const float* W = (const float*)d_in[3];
    float* ctx  = (float*)d_out;                       // [B,H,L,Dv]
    float* attn = ctx + (size_t)BH_ * L_ * DV_;        // [B,H,L,L]

    const int smem1 = 5 * TS_ * (int)sizeof(float);    // 87,040 B
    cudaFuncSetAttribute(logits_kernel,
                         cudaFuncAttributeMaxDynamicSharedMemorySize, smem1);

    dim3 g1(L_ / 64, L_ / 64, BH_);                    // (16,16,128)
    logits_kernel<<<g1, 256, smem1>>>(Q, K, W, attn);

    softmax_add_kernel<<<BH_ * L_, 128>>>(attn);

    dim3 g3(L_ / 64, BH_);                             // (16,128)
    av_kernel<<<g3, 256>>>(attn, V, ctx);
}

// round 3
// speedup vs baseline: 2.2666x; 2.2666x over previous
#include <cuda_runtime.h>
#include <cuda_bf16.h>
#include <cstdint>

#define B_  16
#define H_  8
#define L_  1024
#define DK_ 64
#define BH_ 128
#define SCALE_ 0.125f

// ---------------------------------------------------------------------------
// Device scratch
// ---------------------------------------------------------------------------
__device__ float g_l1[(size_t)BH_ * L_ * L_];
__device__ __nv_bfloat16 g_cath[(size_t)BH_ * L_ * 128];  // [bh][row][Q|K]
__device__ __nv_bfloat16 g_catl[(size_t)BH_ * L_ * 128];
__device__ __nv_bfloat16 g_Wh[(size_t)H_ * L_ * 128];     // pre-scaled by 0.125
__device__ __nv_bfloat16 g_Wl[(size_t)H_ * L_ * 128];
__device__ __nv_bfloat16 g_Vth[(size_t)BH_ * DK_ * L_];   // [bh][d][k]
__device__ __nv_bfloat16 g_Vtl[(size_t)BH_ * DK_ * L_];

// ---------------------------------------------------------------------------
// bf16 mma.sync (sm_80+ PTX; no arch-feature instructions)
// ---------------------------------------------------------------------------
__device__ __forceinline__ void mma_bf16(float (&c)[4], const uint32_t (&a)[4],
                                         const uint32_t (&b)[2]) {
    asm volatile(
        "mma.sync.aligned.m16n8k16.row.col.f32.bf16.bf16.f32 "
        "{%0,%1,%2,%3}, {%4,%5,%6,%7}, {%8,%9}, {%0,%1,%2,%3};\n"
        : "+f"(c[0]), "+f"(c[1]), "+f"(c[2]), "+f"(c[3])
        : "r"(a[0]), "r"(a[1]), "r"(a[2]), "r"(a[3]), "r"(b[0]), "r"(b[1]));
}

__device__ __forceinline__ void split_pack4(const float* f, uint2& hp, uint2& lp) {
    unsigned short* hw = (unsigned short*)&hp;
    unsigned short* lw = (unsigned short*)&lp;
    #pragma unroll
    for (int k = 0; k < 4; k++) {
        __nv_bfloat16 hb = __float2bfloat16(f[k]);
        float r = f[k] - __bfloat162float(hb);
        hw[k] = __bfloat16_as_ushort(hb);
        lw[k] = __bfloat16_as_ushort(__float2bfloat16(r));
    }
}

// ---------------------------------------------------------------------------
// Prep: cat = [Q|K] hi/lo split.  One thread per float4 quad.
// ---------------------------------------------------------------------------
__global__ void cat_kernel(const float* __restrict__ Q, const float* __restrict__ K) {
    int tid = blockIdx.x * blockDim.x + threadIdx.x;   // BH_*L_*32 total
    int q = tid & 31;
    size_t row = (size_t)(tid >> 5);
    const float* src = (q < 16) ? (Q + row * 64 + q * 4)
                                : (K + row * 64 + (q - 16) * 4);
    int col = (q < 16) ? q * 4 : 64 + (q - 16) * 4;
    float4 v = *(const float4*)src;
    float f[4] = {v.x, v.y, v.z, v.w};
    uint2 hp, lp;
    split_pack4(f, hp, lp);
    *(uint2*)(g_cath + row * 128 + col) = hp;
    *(uint2*)(g_catl + row * 128 + col) = lp;
}

// Prep: W * 0.125 hi/lo split.
__global__ void wsplit_kernel(const float* __restrict__ W) {
    int tid = blockIdx.x * blockDim.x + threadIdx.x;   // H_*L_*32 total
    float4 v = ((const float4*)W)[tid];
    float f[4] = {v.x * SCALE_, v.y * SCALE_, v.z * SCALE_, v.w * SCALE_};
    uint2 hp, lp;
    split_pack4(f, hp, lp);
    *(uint2*)(g_Wh + (size_t)tid * 4) = hp;
    *(uint2*)(g_Wl + (size_t)tid * 4) = lp;
}

// Prep: V [bh][k][d] -> Vt hi/lo [bh][d][k]
__global__ void vtrans_kernel(const float* __restrict__ V) {
    __shared__ float tile[64][65];
    int bh = blockIdx.y, k0 = blockIdx.x << 6, t = threadIdx.x;
    const float* src = V + ((size_t)bh * L_ + k0) * DK_;
    #pragma unroll
    for (int i = 0; i < 16; i++) {
        int lin = t + i * 256;
        int r = lin >> 6, d = lin & 63;
        tile[r][d] = src[r * DK_ + d];
    }
    __syncthreads();
    #pragma unroll
    for (int i = 0; i < 16; i++) {
        int lin = t + i * 256;
        int d = lin >> 6, c = lin & 63;
        float x = tile[c][d];
        __nv_bfloat16 hb = __float2bfloat16(x);
        float r = x - __bfloat162float(hb);
        size_t o = ((size_t)bh * DK_ + d) * L_ + k0 + c;
        g_Vth[o] = hb;
        g_Vtl[o] = __float2bfloat16(r);
    }
}

// ---------------------------------------------------------------------------
// Generic 128x128-tile logits GEMM, 3-pass bf16 split.
// MODE 0: l1 = Q.K^T (K=64, A=cat[:,0:64], B=cat[:,64:128], scale at store)
// MODE 1: l2 = W.cat^T (K=128, W pre-scaled)
// 256 threads, 8 warps (4x2), warp tile 32x64.
// smem row-major [row][KD+8] (conflict-free fragment LDS).
// ---------------------------------------------------------------------------
template <int MODE>
__global__ void __launch_bounds__(256) mm_logits_kernel(float* __restrict__ l2out) {
    constexpr int KD = (MODE == 0) ? 64 : 128;
    constexpr int ST = KD + 8;
    extern __shared__ __align__(16) __nv_bfloat16 sm[];
    __nv_bfloat16* sAh = sm;
    __nv_bfloat16* sAl = sm + 128 * ST;
    __nv_bfloat16* sBh = sm + 2 * 128 * ST;
    __nv_bfloat16* sBl = sm + 3 * 128 * ST;

    const int t = threadIdx.x;
    const int bh = blockIdx.z, h = bh & (H_ - 1);
    const int q0 = blockIdx.x << 7;
    const int n0 = blockIdx.y << 7;

    const __nv_bfloat16 *Ah, *Al, *Bh, *Bl;
    if (MODE == 0) {
        size_t base = (size_t)bh * L_ * 128;
        Ah = g_cath + base + (size_t)q0 * 128;
        Al = g_catl + base + (size_t)q0 * 128;
        Bh = g_cath + base + (size_t)n0 * 128 + 64;
        Bl = g_catl + base + (size_t)n0 * 128 + 64;
    } else {
        Ah = g_Wh + ((size_t)h * L_ + q0) * 128;
        Al = g_Wl + ((size_t)h * L_ + q0) * 128;
        Bh = g_cath + ((size_t)bh * L_ + n0) * 128;
        Bl = g_catl + ((size_t)bh * L_ + n0) * 128;
    }

    // Stage tiles: 128 rows x KD bf16, gmem row stride 128.
    constexpr int CPR = KD / 8;            // uint4 chunks per row
    constexpr int ITERS = 128 * CPR / 256;
    #pragma unroll
    for (int i = 0; i < ITERS; i++) {
        int lin = t + i * 256;
        int row = lin / CPR, pc = lin % CPR;
        *(uint4*)(sAh + row * ST + pc * 8) = *(const uint4*)(Ah + (size_t)row * 128 + pc * 8);
        *(uint4*)(sAl + row * ST + pc * 8) = *(const uint4*)(Al + (size_t)row * 128 + pc * 8);
        *(uint4*)(sBh + row * ST + pc * 8) = *(const uint4*)(Bh + (size_t)row * 128 + pc * 8);
        *(uint4*)(sBl + row * ST + pc * 8) = *(const uint4*)(Bl + (size_t)row * 128 + pc * 8);
    }
    __syncthreads();

    const int w = t >> 5, lane = t & 31;
    const int wm = (w >> 1) << 5;          // 0,32,64,96
    const int wn = (w & 1) << 6;           // 0,64
    const int gid = lane >> 2, tig = lane & 3;

    float acc[2][8][4] = {};

    #pragma unroll
    for (int k0 = 0; k0 < KD; k0 += 16) {
        uint32_t ah[2][4], al[2][4];
        #pragma unroll
        for (int i = 0; i < 2; i++) {
            int r = wm + i * 16 + gid;
            ah[i][0] = *(const uint32_t*)(sAh + r * ST + k0 + tig * 2);
            ah[i][1] = *(const uint32_t*)(sAh + (r + 8) * ST + k0 + tig * 2);
            ah[i][2] = *(const uint32_t*)(sAh + r * ST + k0 + tig * 2 + 8);
            ah[i][3] = *(const uint32_t*)(sAh + (r + 8) * ST + k0 + tig * 2 + 8);
            al[i][0] = *(const uint32_t*)(sAl + r * ST + k0 + tig * 2);
            al[i][1] = *(const uint32_t*)(sAl + (r + 8) * ST + k0 + tig * 2);
            al[i][2] = *(const uint32_t*)(sAl + r * ST + k0 + tig * 2 + 8);
            al[i][3] = *(const uint32_t*)(sAl + (r + 8) * ST + k0 + tig * 2 + 8);
        }
        uint32_t bhf[8][2], blf[8][2];
        #pragma unroll
        for (int j = 0; j < 8; j++) {
            int r = wn + j * 8 + gid;
            bhf[j][0] = *(const uint32_t*)(sBh + r * ST + k0 + tig * 2);
            bhf[j][1] = *(const uint32_t*)(sBh + r * ST + k0 + tig * 2 + 8);
            blf[j][0] = *(const uint32_t*)(sBl + r * ST + k0 + tig * 2);
            blf[j][1] = *(const uint32_t*)(sBl + r * ST + k0 + tig * 2 + 8);
        }
        #pragma unroll
        for (int i = 0; i < 2; i++)
            #pragma unroll
            for (int j = 0; j < 8; j++) {
                mma_bf16(acc[i][j], ah[i], bhf[j]);
                mma_bf16(acc[i][j], ah[i], blf[j]);
                mma_bf16(acc[i][j], al[i], bhf[j]);
            }
    }

    float* out = (MODE == 0) ? g_l1 : l2out;
    const float s = (MODE == 0) ? SCALE_ : 1.0f;
    #pragma unroll
    for (int i = 0; i < 2; i++) {
        #pragma unroll
        for (int j = 0; j < 8; j++) {
            int m = q0 + wm + i * 16 + gid;
            int n = n0 + wn + j * 8 + tig * 2;
            float2 v0 = make_float2(acc[i][j][0] * s, acc[i][j][1] * s);
            float2 v1 = make_float2(acc[i][j][2] * s, acc[i][j][3] * s);
            *(float2*)(out + ((size_t)bh * L_ + m) * L_ + n) = v0;
            *(float2*)(out + ((size_t)bh * L_ + m + 8) * L_ + n) = v1;
        }
    }
}

// ---------------------------------------------------------------------------
// Kernel 2: per-row dual softmax + add.
// ---------------------------------------------------------------------------
__global__ void softmax_add_kernel(float* __restrict__ attn) {
    const int row = blockIdx.x;
    const float* r1 = g_l1 + (size_t)row * L_;
    float* r2 = attn + (size_t)row * L_;
    const int t = threadIdx.x;

    float a[8], b[8];
    #pragma unroll
    for (int i = 0; i < 8; i++) { a[i] = r1[t + i * 128]; b[i] = r2[t + i * 128]; }

    float m1 = -1e30f, m2 = -1e30f;
    #pragma unroll
    for (int i = 0; i < 8; i++) { m1 = fmaxf(m1, a[i]); m2 = fmaxf(m2, b[i]); }
    #pragma unroll
    for (int o = 16; o > 0; o >>= 1) {
        m1 = fmaxf(m1, __shfl_xor_sync(0xffffffffu, m1, o));
        m2 = fmaxf(m2, __shfl_xor_sync(0xffffffffu, m2, o));
    }
    __shared__ float sA[4], sB[4];
    const int wid = t >> 5, lid = t & 31;
    if (lid == 0) { sA[wid] = m1; sB[wid] = m2; }
    __syncthreads();
    m1 = fmaxf(fmaxf(sA[0], sA[1]), fmaxf(sA[2], sA[3]));
    m2 = fmaxf(fmaxf(sB[0], sB[1]), fmaxf(sB[2], sB[3]));
    __syncthreads();

    float e1 = 0.f, e2 = 0.f;
    #pragma unroll
    for (int i = 0; i < 8; i++) {
        a[i] = __expf(a[i] - m1); e1 += a[i];
        b[i] = __expf(b[i] - m2); e2 += b[i];
    }
    #pragma unroll
    for (int o = 16; o > 0; o >>= 1) {
        e1 += __shfl_xor_sync(0xffffffffu, e1, o);
        e2 += __shfl_xor_sync(0xffffffffu, e2, o);
    }
    if (lid == 0) { sA[wid] = e1; sB[wid] = e2; }
    __syncthreads();
    e1 = sA[0] + sA[1] + sA[2] + sA[3];
    e2 = sB[0] + sB[1] + sB[2] + sB[3];

    const float inv1 = 1.f / e1, inv2 = 1.f / e2;
    #pragma unroll
    for (int i = 0; i < 8; i++)
        r2[t + i * 128] = a[i] * inv1 + b[i] * inv2;
}

// ---------------------------------------------------------------------------
// Kernel 3: context = attn @ V via mma.sync, attn split on the fly.
// CTA: (q0=128, bh). N=64. K loop: 16 chunks of 64.
// 8 warps (4x2), warp tile 32x32.
// ---------------------------------------------------------------------------
__global__ void __launch_bounds__(256) av_mm_kernel(const float* __restrict__ attn,
                                                    float* __restrict__ ctx) {
    constexpr int ST = 72;
    extern __shared__ __align__(16) __nv_bfloat16 sm[];
    __nv_bfloat16* sAh = sm;                   // 128 x ST
    __nv_bfloat16* sAl = sm + 128 * ST;
    __nv_bfloat16* sVh = sm + 2 * 128 * ST;    // 64 x ST
    __nv_bfloat16* sVl = sm + 2 * 128 * ST + 64 * ST;

    const int t = threadIdx.x;
    const int bh = blockIdx.y;
    const int q0 = blockIdx.x << 7;

    const int w = t >> 5, lane = t & 31;
    const int wm = (w >> 1) << 5;    // 0..96
    const int wn = (w & 1) << 5;     // 0,32
    const int gid = lane >> 2, tig = lane & 3;

    float acc[2][4][4] = {};

    for (int kt = 0; kt < 16; kt++) {
        const int k0 = kt << 6;
        // attn tile [128][64] fp32 -> hi/lo
        const float* ap = attn + ((size_t)bh * L_ + q0) * L_ + k0;
        #pragma unroll
        for (int i = 0; i < 8; i++) {
            int lin = t + i * 256;           // 2048 quads
            int row = lin >> 4, pc = lin & 15;
            float4 v = *(const float4*)(ap + (size_t)row * L_ + pc * 4);
            float f[4] = {v.x, v.y, v.z, v.w};
            uint2 hp, lp;
            split_pack4(f, hp, lp);
            *(uint2*)(sAh + row * ST + pc * 4) = hp;
            *(uint2*)(sAl + row * ST + pc * 4) = lp;
        }
        // Vt tiles [64][64] hi/lo
        #pragma unroll
        for (int i = 0; i < 4; i++) {
            int lin = t + i * 256;           // 1024 chunks
            int tile = lin >> 9, r = (lin >> 3) & 63, pc = lin & 7;
            const __nv_bfloat16* vs =
                (tile ? g_Vtl : g_Vth) + ((size_t)bh * DK_ + r) * L_ + k0 + pc * 8;
            __nv_bfloat16* vd = (tile ? sVl : sVh) + r * ST + pc * 8;
            *(uint4*)vd = *(const uint4*)vs;
        }
        __syncthreads();

        #pragma unroll
        for (int k1 = 0; k1 < 64; k1 += 16) {
            uint32_t ah[2][4], al[2][4];
            #pragma unroll
            for (int i = 0; i < 2; i++) {
                int r = wm + i * 16 + gid;
                ah[i][0] = *(const uint32_t*)(sAh + r * ST + k1 + tig * 2);
                ah[i][1] = *(const uint32_t*)(sAh + (r + 8) * ST + k1 + tig * 2);
                ah[i][2] = *(const uint32_t*)(sAh + r * ST + k1 + tig * 2 + 8);
                ah[i][3] = *(const uint32_t*)(sAh + (r + 8) * ST + k1 + tig * 2 + 8);
                al[i][0] = *(const uint32_t*)(sAl + r * ST + k1 + tig * 2);
                al[i][1] = *(const uint32_t*)(sAl + (r + 8) * ST + k1 + tig * 2);
                al[i][2] = *(const uint32_t*)(sAl + r * ST + k1 + tig * 2 + 8);
                al[i][3] = *(const uint32_t*)(sAl + (r + 8) * ST + k1 + tig * 2 + 8);
            }
            uint32_t bhf[4][2], blf[4][2];
            #pragma unroll
            for (int j = 0; j < 4; j++) {
                int r = wn + j * 8 + gid;
                bhf[j][0] = *(const uint32_t*)(sVh + r * ST + k1 + tig * 2);
                bhf[j][1] = *(const uint32_t*)(sVh + r * ST + k1 + tig * 2 + 8);
                blf[j][0] = *(const uint32_t*)(sVl + r * ST + k1 + tig * 2);
                blf[j][1] = *(const uint32_t*)(sVl + r * ST + k1 + tig * 2 + 8);
            }
            #pragma unroll
            for (int i = 0; i < 2; i++)
                #pragma unroll
                for (int j = 0; j < 4; j++) {
                    mma_bf16(acc[i][j], ah[i], bhf[j]);
                    mma_bf16(acc[i][j], ah[i], blf[j]);
                    mma_bf16(acc[i][j], al[i], bhf[j]);
                }
        }
        __syncthreads();
    }

    #pragma unroll
    for (int i = 0; i < 2; i++)
        #pragma unroll
        for (int j = 0; j < 4; j++) {
            int m = q0 + wm + i * 16 + gid;
            int n = wn + j * 8 + tig * 2;
            *(float2*)(ctx + ((size_t)bh * L_ + m) * DK_ + n) =
                make_float2(acc[i][j][0], acc[i][j][1]);
            *(float2*)(ctx + ((size_t)bh * L_ + m + 8) * DK_ + n) =
                make_float2(acc[i][j][2], acc[i][j][3]);
        }
}

// ---------------------------------------------------------------------------
extern "C" void kernel_launch(void* const* d_in, const int* in_sizes, int n_in,
                              void* d_out, int out_size) {
    const float* Q = (const float*)d_in[0];
    const float* K = (const float*)d_in[1];
    const float* V = (const float*)d_in[2];
    const float* W = (const float*)d_in[3];
    float* ctx  = (float*)d_out;                    // [B,H,L,Dv]
    float* attn = ctx + (size_t)BH_ * L_ * DK_;     // [B,H,L,L]

    // Prep
    cat_kernel<<<BH_ * L_ * 32 / 256, 256>>>(Q, K);
    wsplit_kernel<<<H_ * L_ * 32 / 256, 256>>>(W);
    vtrans_kernel<<<dim3(L_ / 64, BH_), 256>>>(V);

    // Logits
    const int smem0 = 4 * 128 * (64 + 8) * 2;   // 73,728
    const int smem1 = 4 * 128 * (128 + 8) * 2;  // 139,264
    cudaFuncSetAttribute(mm_logits_kernel<0>,
                         cudaFuncAttributeMaxDynamicSharedMemorySize, smem0);
    cudaFuncSetAttribute(mm_logits_kernel<1>,
                         cudaFuncAttributeMaxDynamicSharedMemorySize, smem1);
    mm_logits_kernel<0><<<dim3(8, 8, BH_), 256, smem0>>>(attn);
    mm_logits_kernel<1><<<dim3(8, 8, BH_), 256, smem1>>>(attn);

    // Dual softmax + add
    softmax_add_kernel<<<BH_ * L_, 128>>>(attn);

    // AV
    const int smemAV = (2 * 128 * 72 + 2 * 64 * 72) * 2;  // 55,296
    cudaFuncSetAttribute(av_mm_kernel,
                         cudaFuncAttributeMaxDynamicSharedMemorySize, smemAV);
    av_mm_kernel<<<dim3(8, BH_), 256, smemAV>>>(attn, ctx);
}